// round 13
// baseline (speedup 1.0000x reference)
#include <cuda_runtime.h>
#include <cuda_bf16.h>

#define NB_MAX    16
#define CDIM      256
#define GEM_EPSF  1e-6f
#define NORM_EPSF 1e-12f
#define CHUNK     32

// Scratch (allocation-free). Zeroed at module load; the fused finalize tail
// re-zeroes everything after use, so the invariant holds across graph replays.
__device__ float        g_sums[NB_MAX * CDIM];
__device__ float        g_counts[NB_MAX];
__device__ unsigned int g_ticket;

template <bool CUBE>
__device__ __forceinline__ float gem1(float x, float pv) {
    float v = fmaxf(x, GEM_EPSF);
    return CUBE ? v * v * v : powf(v, pv);
}

template <bool CUBE>
__device__ __forceinline__ void acc4(float4& acc, const float4& x, float pv) {
    acc.x += gem1<CUBE>(x.x, pv);
    acc.y += gem1<CUBE>(x.y, pv);
    acc.z += gem1<CUBE>(x.z, pv);
    acc.w += gem1<CUBE>(x.w, pv);
}

__device__ __forceinline__ void flush_acc(
    float* s_acc, float* s_cnt, int cur_b, int c4,
    float4& acc, int& cnt)
{
    float* dst = s_acc + cur_b * CDIM + 4 * c4;
    if (acc.x != 0.0f || acc.y != 0.0f || acc.z != 0.0f || acc.w != 0.0f) {
        atomicAdd(dst + 0, acc.x);
        atomicAdd(dst + 1, acc.y);
        atomicAdd(dst + 2, acc.z);
        atomicAdd(dst + 3, acc.w);
        acc = make_float4(0.f, 0.f, 0.f, 0.f);
    }
    if (c4 == 0 && cnt) atomicAdd(&s_cnt[cur_b], (float)cnt);
    cnt = 0;
}

// Core accumulation (proven codegen: 8 batched LDG.128 per chunk, MLP=8).
// Fast-path loads use __ldcs (evict-first streaming): the 1GB feature stream
// is read-once, so don't let it churn L2. Thread (rg = tid>>6, c4 = tid&63)
// owns channels 4*c4..4*c4+3 and rows congruent to rg mod 4.
template <bool CUBE>
__device__ __forceinline__ void accum_range(
    const float4* __restrict__ feat4, const int* __restrict__ bidx,
    int r0, int r1, int c4, int rg, float pv, float* s_acc, float* s_cnt)
{
    float4 acc = make_float4(0.f, 0.f, 0.f, 0.f);
    int cnt = 0;
    int cur_b = bidx[r0];
    int r = r0;

    for (; r + CHUNK <= r1; r += CHUNK) {
        // sorted batch_idx: equal endpoints => whole chunk in one segment
        if (bidx[r] == cur_b && bidx[r + CHUNK - 1] == cur_b) {
            float4 v[8];
            #pragma unroll
            for (int k = 0; k < 8; ++k)
                v[k] = __ldcs(feat4 + (size_t)(r + 4 * k + rg) * (CDIM / 4) + c4);
            #pragma unroll
            for (int k = 0; k < 8; ++k) acc4<CUBE>(acc, v[k], pv);
            cnt += 8;   // rows handled by THIS thread in this chunk
        } else {
            // per-row slow path (uniform branch: depends only on shared bidx)
            for (int rr = r; rr < r + CHUNK; ++rr) {
                int b = bidx[rr];
                if (b != cur_b) {
                    flush_acc(s_acc, s_cnt, cur_b, c4, acc, cnt);
                    cur_b = b;
                }
                if (rg == (rr & 3)) {
                    float4 x = feat4[(size_t)rr * (CDIM / 4) + c4];
                    acc4<CUBE>(acc, x, pv);
                    ++cnt;
                }
            }
        }
    }
    for (; r < r1; ++r) {               // tail rows
        int b = bidx[r];
        if (b != cur_b) {
            flush_acc(s_acc, s_cnt, cur_b, c4, acc, cnt);
            cur_b = b;
        }
        if (rg == (r & 3)) {
            float4 x = feat4[(size_t)r * (CDIM / 4) + c4];
            acc4<CUBE>(acc, x, pv);
            ++cnt;
        }
    }
    flush_acc(s_acc, s_cnt, cur_b, c4, acc, cnt);
}

__global__ void __launch_bounds__(256, 4) mink_fused(
    const float4* __restrict__ feat4, const float* __restrict__ p,
    const int* __restrict__ bidx, float* __restrict__ out,
    int n, int rpb, int nb)
{
    __shared__ float s_acc[NB_MAX * CDIM];
    __shared__ float s_cnt[NB_MAX];
    __shared__ unsigned int s_last;
    __shared__ float s_red[8];

    const int tid = threadIdx.x;
    const int c4  = tid & 63;
    const int rg  = tid >> 6;

    #pragma unroll
    for (int k = tid; k < NB_MAX * CDIM; k += 256) s_acc[k] = 0.0f;
    if (tid < NB_MAX) s_cnt[tid] = 0.0f;
    __syncthreads();

    const float pv = p[0];
    const int r0 = (int)blockIdx.x * rpb;
    const int r1 = min(n, r0 + rpb);
    if (r0 < r1) {
        if (pv == 3.0f)
            accum_range<true >(feat4, bidx, r0, r1, c4, rg, pv, s_acc, s_cnt);
        else
            accum_range<false>(feat4, bidx, r0, r1, c4, rg, pv, s_acc, s_cnt);
    }
    __syncthreads();

    // Block -> global (skip zero entries: most blocks touch 1-2 batches).
    #pragma unroll
    for (int b = 0; b < NB_MAX; ++b) {
        float v = s_acc[b * CDIM + tid];
        if (v != 0.0f) atomicAdd(&g_sums[b * CDIM + tid], v);
    }
    if (tid < NB_MAX && s_cnt[tid] != 0.0f) atomicAdd(&g_counts[tid], s_cnt[tid]);

    // ---- last-block finalize (threadFenceReduction pattern) ----
    __threadfence();                 // release: my global sums visible pre-ticket
    __syncthreads();
    if (tid == 0) {
        unsigned int t = atomicAdd(&g_ticket, 1u);
        s_last = (t == gridDim.x - 1) ? 1u : 0u;
    }
    __syncthreads();
    if (s_last == 0u) return;
    __threadfence();                 // acquire side

    const float invp = 1.0f / pv;
    const int lane = tid & 31, warp = tid >> 5;

    float sums[NB_MAX], cnts[NB_MAX];
    #pragma unroll
    for (int b = 0; b < NB_MAX; ++b)                  // MLP=16: all loads first
        sums[b] = __ldcg(&g_sums[b * CDIM + tid]);
    #pragma unroll
    for (int b = 0; b < NB_MAX; ++b)
        cnts[b] = (b < nb) ? __ldcg(&g_counts[b]) : 0.0f;

    #pragma unroll
    for (int b = 0; b < NB_MAX; ++b) {
        if (b >= nb) break;
        float c    = cnts[b];
        float mean = (c > 0.0f) ? sums[b] / c : 0.0f;
        float desc = powf(mean, invp);   // mean >= eps^p > 0 when c>0
        float sq   = desc * desc;
        #pragma unroll
        for (int m = 16; m > 0; m >>= 1)
            sq += __shfl_xor_sync(0xffffffffu, sq, m);
        if (lane == 0) s_red[warp] = sq;
        __syncthreads();
        float tot = s_red[0] + s_red[1] + s_red[2] + s_red[3]
                  + s_red[4] + s_red[5] + s_red[6] + s_red[7];
        out[b * CDIM + tid] = desc / fmaxf(sqrtf(tot), NORM_EPSF);
        __syncthreads();
    }

    // Reset scratch for the next call / graph replay.
    #pragma unroll
    for (int k = tid; k < NB_MAX * CDIM; k += 256) g_sums[k] = 0.0f;
    if (tid < NB_MAX) g_counts[tid] = 0.0f;
    if (tid == 0) g_ticket = 0u;
}

extern "C" void kernel_launch(void* const* d_in, const int* in_sizes, int n_in,
                              void* d_out, int out_size)
{
    const float4* feat4 = (const float4*)d_in[0];
    const float*  p     = (const float*)d_in[1];
    const int*    bidx  = (const int*)d_in[2];

    int n  = in_sizes[2];          // N voxels
    int nb = out_size / CDIM;      // B point clouds
    if (nb > NB_MAX) nb = NB_MAX;

    // ~16 waves at 4 blocks/SM: knee-finding step of the wave-granularity
    // sweep (4->8 waves won 2.7us). Finer quantum shrinks the last-wave
    // straggler tail gating the fused finalize. Rows/block rounded to CHUNK.
    const int target = 148 * 64;
    int rpb = (n + target - 1) / target;
    rpb = (rpb + CHUNK - 1) & ~(CHUNK - 1);
    if (rpb < CHUNK) rpb = CHUNK;
    int grid = (n + rpb - 1) / rpb;

    mink_fused<<<grid, 256>>>(feat4, p, bidx, (float*)d_out, n, rpb, nb);
}